// round 1
// baseline (speedup 1.0000x reference)
#include <cuda_runtime.h>
#include <cstdint>
#include <cstddef>

// Problem constants
#define NB     16
#define NN     256
#define NT     4
#define HD     128
#define NL     2
#define CELLS  (NB*NN)        // 4096
#define LOFF   (CELLS*HD)     // per-layer offset in state arrays
#define MAXST  15
#define OUTV   1000

typedef unsigned long long u64;

// ---------------- device scratch (no allocations allowed) ----------------
__device__ float g_c_cur[NL*CELLS*HD];
__device__ float g_h_cur[NL*CELLS*HD];
__device__ float g_c_wrk[NL*CELLS*HD];
__device__ float g_h_wrk[NL*CELLS*HD];
__device__ float g_emb [CELLS*NT*HD];     // [cell][t][h]
__device__ float g_xw  [CELLS*NT*512];    // precomputed emb @ Wi(layer0), [cell*4+t][512]
__device__ float g_w1  [256*512];         // concat [Wi1; Wh1]
__device__ float g_ip  [CELLS];
__device__ float g_wt  [CELLS];
__device__ float g_wf  [CELLS];

// ---------------- f32x2 packed math helpers ----------------
__device__ __forceinline__ u64 pk2(float x, float y) {
    u64 r; asm("mov.b64 %0, {%1, %2};" : "=l"(r) : "f"(x), "f"(y)); return r;
}
__device__ __forceinline__ float2 upk2(u64 v) {
    float2 r; asm("mov.b64 {%0, %1}, %2;" : "=f"(r.x), "=f"(r.y) : "l"(v)); return r;
}
__device__ __forceinline__ void fma2(u64& d, u64 a, u64 b) {
    asm("fma.rn.f32x2 %0, %1, %2, %0;" : "+l"(d) : "l"(a), "l"(b));
}
__device__ __forceinline__ float sigf(float x)  { return 1.0f / (1.0f + __expf(-x)); }
__device__ __forceinline__ float tanh_(float x) { return 2.0f / (1.0f + __expf(-2.0f*x)) - 1.0f; }

// ---------------- fused GEMM (+ optional LSTM gate epilogue) ----------------
// Computes Z[M,512] = A[M, nslabs*16] @ W[nslabs*16, 512] (+ zinit), then either
// stores Z (gate=0) or applies the LSTM cell update (gate=1).
// A columns [0,128) come from a0 (row stride sa0); columns [128,256) from a1 (stride 128).
// Block: 256 threads, BM=32 rows, BN=512 (all 4 gates). Thread (tr,tc): rows tr*8+r,
// cols 2*tc + j + 128*cI  -> cI indexes gate {i,f,g,o}, (2tc+j) is the h-dim.
__global__ void __launch_bounds__(256) fused_gemm_lstm(
    const float* __restrict__ a0, int sa0,
    const float* __restrict__ a1,
    const float* __restrict__ w,
    const float* __restrict__ zinit, int szinit,
    const float* __restrict__ bias,
    const float* cin, float* cout, float* hout,
    float* zout,
    int nslabs, int gate)
{
    __shared__ float As[16][32];
    __shared__ float Bs[16][512];
    const int tid = threadIdx.x;
    const int tr  = tid >> 6;     // 0..3
    const int tc  = tid & 63;     // 0..63
    const int rowbase = blockIdx.x * 32;

    u64 acc[8][4];
    if (zinit) {
        #pragma unroll
        for (int r = 0; r < 8; ++r) {
            const float* zp = zinit + (size_t)(rowbase + tr*8 + r) * szinit + 2*tc;
            #pragma unroll
            for (int cI = 0; cI < 4; ++cI) acc[r][cI] = *(const u64*)(zp + 128*cI);
        }
    } else {
        #pragma unroll
        for (int r = 0; r < 8; ++r)
            #pragma unroll
            for (int cI = 0; cI < 4; ++cI) acc[r][cI] = 0ull;
    }

    for (int slab = 0; slab < nslabs; ++slab) {
        const int kbase = slab * 16;
        if (tid < 128) {  // load A slab (transposed into As[k][m])
            const int m  = tid >> 2;
            const int kq = (tid & 3) * 4;
            const float* src = (kbase < 128)
                ? a0 + (size_t)(rowbase + m) * sa0 + kbase + kq
                : a1 + (size_t)(rowbase + m) * 128 + (kbase - 128) + kq;
            float4 v = *(const float4*)src;
            As[kq+0][m] = v.x; As[kq+1][m] = v.y; As[kq+2][m] = v.z; As[kq+3][m] = v.w;
        }
        {   // load B slab: 16x512 floats
            const float4* wsrc = (const float4*)(w + (size_t)kbase * 512);
            float4* bdst = (float4*)&Bs[0][0];
            #pragma unroll
            for (int i = 0; i < 8; ++i) bdst[i*256 + tid] = wsrc[i*256 + tid];
        }
        __syncthreads();
        #pragma unroll
        for (int kk = 0; kk < 16; ++kk) {
            u64 b2[4];
            float a[8];
            #pragma unroll
            for (int cI = 0; cI < 4; ++cI)
                b2[cI] = *(const u64*)&Bs[kk][2*tc + 128*cI];
            #pragma unroll
            for (int r = 0; r < 8; ++r) a[r] = As[kk][tr*8 + r];
            #pragma unroll
            for (int r = 0; r < 8; ++r) {
                u64 aa = pk2(a[r], a[r]);
                #pragma unroll
                for (int cI = 0; cI < 4; ++cI) fma2(acc[r][cI], aa, b2[cI]);
            }
        }
        __syncthreads();
    }

    if (gate) {
        float2 bi = *(const float2*)&bias[      2*tc];
        float2 bf = *(const float2*)&bias[128 + 2*tc];
        float2 bg = *(const float2*)&bias[256 + 2*tc];
        float2 bo = *(const float2*)&bias[384 + 2*tc];
        #pragma unroll
        for (int r = 0; r < 8; ++r) {
            const int row = rowbase + tr*8 + r;
            float2 zi = upk2(acc[r][0]);
            float2 zf = upk2(acc[r][1]);
            float2 zg = upk2(acc[r][2]);
            float2 zo = upk2(acc[r][3]);
            zi.x += bi.x; zi.y += bi.y;
            zf.x += bf.x; zf.y += bf.y;
            zg.x += bg.x; zg.y += bg.y;
            zo.x += bo.x; zo.y += bo.y;
            float2 cold = *(const float2*)&cin[(size_t)row*128 + 2*tc];
            float cnx = sigf(zf.x)*cold.x + sigf(zi.x)*tanh_(zg.x);
            float cny = sigf(zf.y)*cold.y + sigf(zi.y)*tanh_(zg.y);
            float hnx = sigf(zo.x)*tanh_(cnx);
            float hny = sigf(zo.y)*tanh_(cny);
            *(float2*)&cout[(size_t)row*128 + 2*tc] = make_float2(cnx, cny);
            *(float2*)&hout[(size_t)row*128 + 2*tc] = make_float2(hnx, hny);
        }
    } else {
        #pragma unroll
        for (int r = 0; r < 8; ++r) {
            const int row = rowbase + tr*8 + r;
            float* zp = zout + (size_t)row * 512 + 2*tc;
            #pragma unroll
            for (int cI = 0; cI < 4; ++cI) *(u64*)(zp + 128*cI) = acc[r][cI];
        }
    }
}

// ---------------- small kernels ----------------
__global__ void gather_kernel(const int* __restrict__ data,
                              const float* __restrict__ embed,
                              float* __restrict__ emb)
{
    int i = blockIdx.x * blockDim.x + threadIdx.x;       // < CELLS*NT*HD
    if (i >= CELLS*NT*HD) return;
    int hh = i & 127;
    int ct = i >> 7;                                     // cell*4 + t
    emb[i] = embed[(size_t)data[ct] * HD + hh];
}

__global__ void wcat1_kernel(const float* __restrict__ Wi,
                             const float* __restrict__ Wh,
                             float* __restrict__ w1)
{
    int i = blockIdx.x * blockDim.x + threadIdx.x;       // < 256*512
    if (i >= 256*512) return;
    int n = i & 511;
    int k = i >> 9;                                      // 0..255
    // layer 1 slices: Wi[(1*128+k)*512+n], Wh[(1*128+(k-128))*512+n]
    w1[i] = (k < 128) ? Wi[(size_t)(128 + k) * 512 + n]
                      : Wh[(size_t)(128 + (k - 128)) * 512 + n];
}

__global__ void ipinit_kernel(float* __restrict__ ip)
{
    if (threadIdx.x < NB) ip[threadIdx.x * NN] = 1.0f;
}

__global__ void restore_kernel(const int* __restrict__ exi,
                               float* __restrict__ cw, float* __restrict__ hw,
                               const float* __restrict__ cc, const float* __restrict__ hc)
{
    int b = blockIdx.x;
    int cell = b * NN + exi[b];
    for (int i = threadIdx.x; i < NL*HD; i += blockDim.x) {
        int l = i >> 7, d = i & 127;
        size_t off = (size_t)l * LOFF + (size_t)cell * HD + d;
        cw[off] = cc[off];
        hw[off] = hc[off];
    }
}

__global__ void branch_kernel(const float* __restrict__ c0, const float* __restrict__ h0,
                              const float* __restrict__ c1, const float* __restrict__ h1,
                              const float* __restrict__ Wb, const float* __restrict__ bb,
                              const float* __restrict__ ip,
                              float* __restrict__ wt, float* __restrict__ wf)
{
    int warp = (blockIdx.x * blockDim.x + threadIdx.x) >> 5;
    int lane = threadIdx.x & 31;
    if (warp >= CELLS) return;
    const float* arrs[4] = {c0, h0, c1, h1};
    float a0 = 0.f, a1 = 0.f;
    #pragma unroll
    for (int q = 0; q < 4; ++q) {
        const float* p = arrs[q] + (size_t)warp * HD;
        #pragma unroll
        for (int d = lane; d < HD; d += 32) {
            float v = p[d];
            float2 wb = *(const float2*)&Wb[2 * (q*HD + d)];
            a0 += v * wb.x;
            a1 += v * wb.y;
        }
    }
    #pragma unroll
    for (int off = 16; off; off >>= 1) {
        a0 += __shfl_xor_sync(0xffffffffu, a0, off);
        a1 += __shfl_xor_sync(0xffffffffu, a1, off);
    }
    if (lane == 0) {
        a0 += bb[0]; a1 += bb[1];
        float m  = fmaxf(a0, a1);
        float e0 = __expf(a0 - m), e1 = __expf(a1 - m);
        float inv = 1.0f / (e0 + e1);
        float w = ip[warp];
        wt[warp] = e0 * inv * w;
        wf[warp] = e1 * inv * w;
    }
}

// Deterministic dst-side gather aggregation (no fp atomics).
__global__ void __launch_bounds__(128) agg_kernel(
    int step,
    const int* __restrict__ steps,
    const int* __restrict__ tb, const int* __restrict__ fb,
    const float* __restrict__ wt, const float* __restrict__ wf,
    const float* __restrict__ cw, const float* __restrict__ hw,
    float* __restrict__ cc, float* __restrict__ hc,
    float* __restrict__ ip)
{
    int cell = blockIdx.x;
    int b = cell >> 8, dst = cell & 255;
    if (step >= steps[b]) return;            // uniform per block

    __shared__ float swt[NN], swf[NN];
    __shared__ int   stb[NN], sfb[NN];
    int tid = threadIdx.x;
    for (int i = tid; i < NN; i += 128) {
        swt[i] = wt[b*NN + i]; swf[i] = wf[b*NN + i];
        stb[i] = tb[b*NN + i]; sfb[i] = fb[b*NN + i];
    }
    __syncthreads();

    float a0 = 0.f, a1 = 0.f, a2 = 0.f, a3 = 0.f, ipn = 0.f;
    for (int s = 0; s < NN; ++s) {
        bool m1 = (stb[s] == dst), m2 = (sfb[s] == dst);
        if (m1 | m2) {
            float w = (m1 ? swt[s] : 0.f) + (m2 ? swf[s] : 0.f);
            ipn += w;
            size_t o0 = (size_t)(b*NN + s) * HD + tid;
            a0 += w * cw[o0];
            a1 += w * hw[o0];
            a2 += w * cw[o0 + LOFF];
            a3 += w * hw[o0 + LOFF];
        }
    }
    float inv = 1.0f / (ipn + 1e-7f);
    size_t od = (size_t)cell * HD + tid;
    cc[od]        = a0 * inv;
    hc[od]        = a1 * inv;
    cc[od + LOFF] = a2 * inv;
    hc[od + LOFF] = a3 * inv;
    if (tid == 0) ip[cell] = ipn;
}

__global__ void final_kernel(const int* __restrict__ exi,
                             const float* __restrict__ cc, const float* __restrict__ hc,
                             const float* __restrict__ Wo, const float* __restrict__ bo,
                             float* __restrict__ out)
{
    int b = blockIdx.x;
    __shared__ float f[4*HD];
    int cell = b * NN + exi[b];
    for (int i = threadIdx.x; i < 4*HD; i += blockDim.x) {
        int l  = i >> 8;          // 0..1
        int ch = (i >> 7) & 1;    // 0=c, 1=h  (order: c0,h0,c1,h1)
        int d  = i & 127;
        const float* src = ch ? hc : cc;
        f[i] = src[(size_t)l * LOFF + (size_t)cell * HD + d];
    }
    __syncthreads();
    for (int o = threadIdx.x; o < OUTV; o += blockDim.x) {
        float acc = bo[o];
        #pragma unroll 8
        for (int k = 0; k < 4*HD; ++k) acc += f[k] * Wo[(size_t)k * OUTV + o];
        out[(size_t)b * OUTV + o] = acc;
    }
}

// ---------------- host ----------------
extern "C" void kernel_launch(void* const* d_in, const int* in_sizes, int n_in,
                              void* d_out, int out_size)
{
    const int*   data  = (const int*)  d_in[0];
    const int*   tb    = (const int*)  d_in[1];
    const int*   fb    = (const int*)  d_in[2];
    const int*   exi   = (const int*)  d_in[3];
    const int*   steps = (const int*)  d_in[4];
    const float* embed = (const float*)d_in[5];
    const float* Wi    = (const float*)d_in[6];
    const float* Wh    = (const float*)d_in[7];
    const float* bl    = (const float*)d_in[8];
    const float* Wb    = (const float*)d_in[9];
    const float* bb    = (const float*)d_in[10];
    const float* Wo    = (const float*)d_in[11];
    const float* bo    = (const float*)d_in[12];
    float* out = (float*)d_out;

    float *c_cur, *h_cur, *c_wrk, *h_wrk, *emb, *xw, *w1, *ip, *wt, *wf;
    cudaGetSymbolAddress((void**)&c_cur, g_c_cur);
    cudaGetSymbolAddress((void**)&h_cur, g_h_cur);
    cudaGetSymbolAddress((void**)&c_wrk, g_c_wrk);
    cudaGetSymbolAddress((void**)&h_wrk, g_h_wrk);
    cudaGetSymbolAddress((void**)&emb,   g_emb);
    cudaGetSymbolAddress((void**)&xw,    g_xw);
    cudaGetSymbolAddress((void**)&w1,    g_w1);
    cudaGetSymbolAddress((void**)&ip,    g_ip);
    cudaGetSymbolAddress((void**)&wt,    g_wt);
    cudaGetSymbolAddress((void**)&wf,    g_wf);

    // init
    cudaMemsetAsync(c_cur, 0, sizeof(float) * NL * CELLS * HD, 0);
    cudaMemsetAsync(h_cur, 0, sizeof(float) * NL * CELLS * HD, 0);
    cudaMemsetAsync(ip,    0, sizeof(float) * CELLS, 0);
    ipinit_kernel<<<1, 32>>>(ip);
    gather_kernel<<<(CELLS*NT*HD + 255) / 256, 256>>>(data, embed, emb);
    wcat1_kernel<<<(256*512 + 255) / 256, 256>>>(Wi, Wh, w1);

    // precompute xw[cell*4+t][512] = emb @ Wi(layer0); M = CELLS*NT rows
    fused_gemm_lstm<<<(CELLS*NT)/32, 256>>>(
        emb, HD, nullptr, Wi,
        nullptr, 0, nullptr, nullptr, nullptr, nullptr,
        xw, 8, 0);

    for (int s = 0; s < MAXST; ++s) {
        for (int t = 0; t < NT; ++t) {
            const float* cin0 = (t == 0) ? c_cur : c_wrk;
            const float* hin0 = (t == 0) ? h_cur : h_wrk;
            // layer 0: z = xw(t) + h @ Wh0 ; gate
            fused_gemm_lstm<<<CELLS/32, 256>>>(
                hin0, HD, nullptr, Wh,
                xw + t*512, NT*512, bl,
                cin0, c_wrk, h_wrk,
                nullptr, 8, 1);
            // layer 1: z = h0 @ Wi1 + h1 @ Wh1 + b ; gate
            const float* cin1 = (t == 0) ? c_cur + LOFF : c_wrk + LOFF;
            const float* hin1 = (t == 0) ? h_cur + LOFF : h_wrk + LOFF;
            fused_gemm_lstm<<<CELLS/32, 256>>>(
                h_wrk, HD, hin1, w1,
                nullptr, 0, bl + 512,
                cin1, c_wrk + LOFF, h_wrk + LOFF,
                nullptr, 16, 1);
        }
        restore_kernel<<<NB, 256>>>(exi, c_wrk, h_wrk, c_cur, h_cur);
        branch_kernel<<<(CELLS*32 + 255) / 256, 256>>>(
            c_wrk, h_wrk, c_wrk + LOFF, h_wrk + LOFF, Wb, bb, ip, wt, wf);
        agg_kernel<<<CELLS, 128>>>(s, steps, tb, fb, wt, wf,
                                   c_wrk, h_wrk, c_cur, h_cur, ip);
    }

    final_kernel<<<NB, 256>>>(exi, c_cur, h_cur, Wo, bo, out);
}

// round 2
// speedup vs baseline: 1.0484x; 1.0484x over previous
#include <cuda_runtime.h>
#include <cstdint>
#include <cstddef>

// Problem constants
#define NB     16
#define NN     256
#define NT     4
#define HD     128
#define NL     2
#define CELLS  (NB*NN)        // 4096
#define LOFF   (CELLS*HD)     // per-layer offset in state arrays
#define MAXST  15
#define OUTV   1000

typedef unsigned long long u64;

// ---------------- device scratch (no allocations allowed) ----------------
__device__ float g_c_cur[NL*CELLS*HD];
__device__ float g_h_cur[NL*CELLS*HD];
__device__ float g_c_wrk[NL*CELLS*HD];
__device__ float g_h_wrk[NL*CELLS*HD];
__device__ float g_emb [CELLS*NT*HD];     // [cell][t][h]
__device__ float g_xw  [CELLS*NT*512];    // precomputed emb @ Wi(layer0), [cell*4+t][512]
__device__ float g_w1  [256*512];         // concat [Wi1; Wh1]
__device__ float g_ip  [CELLS];
__device__ float g_wt  [CELLS];
__device__ float g_wf  [CELLS];

// ---------------- f32x2 packed math helpers ----------------
__device__ __forceinline__ u64 pk2(float x, float y) {
    u64 r; asm("mov.b64 %0, {%1, %2};" : "=l"(r) : "f"(x), "f"(y)); return r;
}
__device__ __forceinline__ float2 upk2(u64 v) {
    float2 r; asm("mov.b64 {%0, %1}, %2;" : "=f"(r.x), "=f"(r.y) : "l"(v)); return r;
}
__device__ __forceinline__ void fma2(u64& d, u64 a, u64 b) {
    asm("fma.rn.f32x2 %0, %1, %2, %0;" : "+l"(d) : "l"(a), "l"(b));
}
__device__ __forceinline__ float sigf(float x)  { return 1.0f / (1.0f + __expf(-x)); }
__device__ __forceinline__ float tanh_(float x) { return 2.0f / (1.0f + __expf(-2.0f*x)) - 1.0f; }

// ---------------- fused GEMM (+ optional LSTM gate epilogue) ----------------
// Computes Z[M,512] = A[M, nslabs*16] @ W[nslabs*16, 512] (+ zinit), then either
// stores Z (gate=0) or applies the LSTM cell update (gate=1).
// A columns [0,128) come from a0 (row stride sa0); columns [128,256) from a1 (stride 128).
// Block: 256 threads, BM=32 rows, BN=512 (all 4 gates). Thread (tr,tc): rows tr*8+r,
// cols 2*tc + j + 128*cI  -> cI indexes gate {i,f,g,o}, (2tc+j) is the h-dim.
__global__ void __launch_bounds__(256) fused_gemm_lstm(
    const float* __restrict__ a0, int sa0,
    const float* __restrict__ a1,
    const float* __restrict__ w,
    const float* __restrict__ zinit, int szinit,
    const float* __restrict__ bias,
    const float* cin, float* cout, float* hout,
    float* zout,
    int nslabs, int gate)
{
    __shared__ float As[16][32];
    __shared__ float Bs[16][512];
    const int tid = threadIdx.x;
    const int tr  = tid >> 6;     // 0..3
    const int tc  = tid & 63;     // 0..63
    const int rowbase = blockIdx.x * 32;

    u64 acc[8][4];
    if (zinit) {
        #pragma unroll
        for (int r = 0; r < 8; ++r) {
            const float* zp = zinit + (size_t)(rowbase + tr*8 + r) * szinit + 2*tc;
            #pragma unroll
            for (int cI = 0; cI < 4; ++cI) acc[r][cI] = *(const u64*)(zp + 128*cI);
        }
    } else {
        #pragma unroll
        for (int r = 0; r < 8; ++r)
            #pragma unroll
            for (int cI = 0; cI < 4; ++cI) acc[r][cI] = 0ull;
    }

    for (int slab = 0; slab < nslabs; ++slab) {
        const int kbase = slab * 16;
        if (tid < 128) {  // load A slab (transposed into As[k][m])
            const int m  = tid >> 2;
            const int kq = (tid & 3) * 4;
            const float* src = (kbase < 128)
                ? a0 + (size_t)(rowbase + m) * sa0 + kbase + kq
                : a1 + (size_t)(rowbase + m) * 128 + (kbase - 128) + kq;
            float4 v = *(const float4*)src;
            As[kq+0][m] = v.x; As[kq+1][m] = v.y; As[kq+2][m] = v.z; As[kq+3][m] = v.w;
        }
        {   // load B slab: 16x512 floats
            const float4* wsrc = (const float4*)(w + (size_t)kbase * 512);
            float4* bdst = (float4*)&Bs[0][0];
            #pragma unroll
            for (int i = 0; i < 8; ++i) bdst[i*256 + tid] = wsrc[i*256 + tid];
        }
        __syncthreads();
        #pragma unroll
        for (int kk = 0; kk < 16; ++kk) {
            u64 b2[4];
            float a[8];
            #pragma unroll
            for (int cI = 0; cI < 4; ++cI)
                b2[cI] = *(const u64*)&Bs[kk][2*tc + 128*cI];
            #pragma unroll
            for (int r = 0; r < 8; ++r) a[r] = As[kk][tr*8 + r];
            #pragma unroll
            for (int r = 0; r < 8; ++r) {
                u64 aa = pk2(a[r], a[r]);
                #pragma unroll
                for (int cI = 0; cI < 4; ++cI) fma2(acc[r][cI], aa, b2[cI]);
            }
        }
        __syncthreads();
    }

    if (gate) {
        float2 bi = *(const float2*)&bias[      2*tc];
        float2 bf = *(const float2*)&bias[128 + 2*tc];
        float2 bg = *(const float2*)&bias[256 + 2*tc];
        float2 bo = *(const float2*)&bias[384 + 2*tc];
        #pragma unroll
        for (int r = 0; r < 8; ++r) {
            const int row = rowbase + tr*8 + r;
            float2 zi = upk2(acc[r][0]);
            float2 zf = upk2(acc[r][1]);
            float2 zg = upk2(acc[r][2]);
            float2 zo = upk2(acc[r][3]);
            zi.x += bi.x; zi.y += bi.y;
            zf.x += bf.x; zf.y += bf.y;
            zg.x += bg.x; zg.y += bg.y;
            zo.x += bo.x; zo.y += bo.y;
            float2 cold = *(const float2*)&cin[(size_t)row*128 + 2*tc];
            float cnx = sigf(zf.x)*cold.x + sigf(zi.x)*tanh_(zg.x);
            float cny = sigf(zf.y)*cold.y + sigf(zi.y)*tanh_(zg.y);
            float hnx = sigf(zo.x)*tanh_(cnx);
            float hny = sigf(zo.y)*tanh_(cny);
            *(float2*)&cout[(size_t)row*128 + 2*tc] = make_float2(cnx, cny);
            *(float2*)&hout[(size_t)row*128 + 2*tc] = make_float2(hnx, hny);
        }
    } else {
        #pragma unroll
        for (int r = 0; r < 8; ++r) {
            const int row = rowbase + tr*8 + r;
            float* zp = zout + (size_t)row * 512 + 2*tc;
            #pragma unroll
            for (int cI = 0; cI < 4; ++cI) *(u64*)(zp + 128*cI) = acc[r][cI];
        }
    }
}

// ---------------- small kernels ----------------
__global__ void gather_kernel(const int* __restrict__ data,
                              const float* __restrict__ embed,
                              float* __restrict__ emb)
{
    int i = blockIdx.x * blockDim.x + threadIdx.x;       // < CELLS*NT*HD
    if (i >= CELLS*NT*HD) return;
    int hh = i & 127;
    int ct = i >> 7;                                     // cell*4 + t
    emb[i] = embed[(size_t)data[ct] * HD + hh];
}

__global__ void wcat1_kernel(const float* __restrict__ Wi,
                             const float* __restrict__ Wh,
                             float* __restrict__ w1)
{
    int i = blockIdx.x * blockDim.x + threadIdx.x;       // < 256*512
    if (i >= 256*512) return;
    int n = i & 511;
    int k = i >> 9;                                      // 0..255
    // layer 1 slices: Wi[(1*128+k)*512+n], Wh[(1*128+(k-128))*512+n]
    w1[i] = (k < 128) ? Wi[(size_t)(128 + k) * 512 + n]
                      : Wh[(size_t)(128 + (k - 128)) * 512 + n];
}

__global__ void ipinit_kernel(float* __restrict__ ip)
{
    if (threadIdx.x < NB) ip[threadIdx.x * NN] = 1.0f;
}

__global__ void restore_kernel(const int* __restrict__ exi,
                               float* __restrict__ cw, float* __restrict__ hw,
                               const float* __restrict__ cc, const float* __restrict__ hc)
{
    int b = blockIdx.x;
    int cell = b * NN + exi[b];
    for (int i = threadIdx.x; i < NL*HD; i += blockDim.x) {
        int l = i >> 7, d = i & 127;
        size_t off = (size_t)l * LOFF + (size_t)cell * HD + d;
        cw[off] = cc[off];
        hw[off] = hc[off];
    }
}

__global__ void branch_kernel(const float* __restrict__ c0, const float* __restrict__ h0,
                              const float* __restrict__ c1, const float* __restrict__ h1,
                              const float* __restrict__ Wb, const float* __restrict__ bb,
                              const float* __restrict__ ip,
                              float* __restrict__ wt, float* __restrict__ wf)
{
    int warp = (blockIdx.x * blockDim.x + threadIdx.x) >> 5;
    int lane = threadIdx.x & 31;
    if (warp >= CELLS) return;
    const float* arrs[4] = {c0, h0, c1, h1};
    float a0 = 0.f, a1 = 0.f;
    #pragma unroll
    for (int q = 0; q < 4; ++q) {
        const float* p = arrs[q] + (size_t)warp * HD;
        #pragma unroll
        for (int d = lane; d < HD; d += 32) {
            float v = p[d];
            float2 wb = *(const float2*)&Wb[2 * (q*HD + d)];
            a0 += v * wb.x;
            a1 += v * wb.y;
        }
    }
    #pragma unroll
    for (int off = 16; off; off >>= 1) {
        a0 += __shfl_xor_sync(0xffffffffu, a0, off);
        a1 += __shfl_xor_sync(0xffffffffu, a1, off);
    }
    if (lane == 0) {
        a0 += bb[0]; a1 += bb[1];
        float m  = fmaxf(a0, a1);
        float e0 = __expf(a0 - m), e1 = __expf(a1 - m);
        float inv = 1.0f / (e0 + e1);
        float w = ip[warp];
        wt[warp] = e0 * inv * w;
        wf[warp] = e1 * inv * w;
    }
}

// Deterministic dst-side gather aggregation (no fp atomics).
__global__ void __launch_bounds__(128) agg_kernel(
    int step,
    const int* __restrict__ steps,
    const int* __restrict__ tb, const int* __restrict__ fb,
    const float* __restrict__ wt, const float* __restrict__ wf,
    const float* __restrict__ cw, const float* __restrict__ hw,
    float* __restrict__ cc, float* __restrict__ hc,
    float* __restrict__ ip)
{
    int cell = blockIdx.x;
    int b = cell >> 8, dst = cell & 255;
    if (step >= steps[b]) return;            // uniform per block

    __shared__ float swt[NN], swf[NN];
    __shared__ int   stb[NN], sfb[NN];
    int tid = threadIdx.x;
    for (int i = tid; i < NN; i += 128) {
        swt[i] = wt[b*NN + i]; swf[i] = wf[b*NN + i];
        stb[i] = tb[b*NN + i]; sfb[i] = fb[b*NN + i];
    }
    __syncthreads();

    float a0 = 0.f, a1 = 0.f, a2 = 0.f, a3 = 0.f, ipn = 0.f;
    for (int s = 0; s < NN; ++s) {
        bool m1 = (stb[s] == dst), m2 = (sfb[s] == dst);
        if (m1 | m2) {
            float w = (m1 ? swt[s] : 0.f) + (m2 ? swf[s] : 0.f);
            ipn += w;
            size_t o0 = (size_t)(b*NN + s) * HD + tid;
            a0 += w * cw[o0];
            a1 += w * hw[o0];
            a2 += w * cw[o0 + LOFF];
            a3 += w * hw[o0 + LOFF];
        }
    }
    float inv = 1.0f / (ipn + 1e-7f);
    size_t od = (size_t)cell * HD + tid;
    cc[od]        = a0 * inv;
    hc[od]        = a1 * inv;
    cc[od + LOFF] = a2 * inv;
    hc[od + LOFF] = a3 * inv;
    if (tid == 0) ip[cell] = ipn;
}

__global__ void final_kernel(const int* __restrict__ exi,
                             const float* __restrict__ cc, const float* __restrict__ hc,
                             const float* __restrict__ Wo, const float* __restrict__ bo,
                             float* __restrict__ out)
{
    int b = blockIdx.x;
    __shared__ float f[4*HD];
    int cell = b * NN + exi[b];
    for (int i = threadIdx.x; i < 4*HD; i += blockDim.x) {
        int l  = i >> 8;          // 0..1
        int ch = (i >> 7) & 1;    // 0=c, 1=h  (order: c0,h0,c1,h1)
        int d  = i & 127;
        const float* src = ch ? hc : cc;
        f[i] = src[(size_t)l * LOFF + (size_t)cell * HD + d];
    }
    __syncthreads();
    for (int o = threadIdx.x; o < OUTV; o += blockDim.x) {
        float acc = bo[o];
        #pragma unroll 8
        for (int k = 0; k < 4*HD; ++k) acc += f[k] * Wo[(size_t)k * OUTV + o];
        out[(size_t)b * OUTV + o] = acc;
    }
}

// ---------------- host ----------------
extern "C" void kernel_launch(void* const* d_in, const int* in_sizes, int n_in,
                              void* d_out, int out_size)
{
    const int*   data  = (const int*)  d_in[0];
    const int*   tb    = (const int*)  d_in[1];
    const int*   fb    = (const int*)  d_in[2];
    const int*   exi   = (const int*)  d_in[3];
    const int*   steps = (const int*)  d_in[4];
    const float* embed = (const float*)d_in[5];
    const float* Wi    = (const float*)d_in[6];
    const float* Wh    = (const float*)d_in[7];
    const float* bl    = (const float*)d_in[8];
    const float* Wb    = (const float*)d_in[9];
    const float* bb    = (const float*)d_in[10];
    const float* Wo    = (const float*)d_in[11];
    const float* bo    = (const float*)d_in[12];
    float* out = (float*)d_out;

    float *c_cur, *h_cur, *c_wrk, *h_wrk, *emb, *xw, *w1, *ip, *wt, *wf;
    cudaGetSymbolAddress((void**)&c_cur, g_c_cur);
    cudaGetSymbolAddress((void**)&h_cur, g_h_cur);
    cudaGetSymbolAddress((void**)&c_wrk, g_c_wrk);
    cudaGetSymbolAddress((void**)&h_wrk, g_h_wrk);
    cudaGetSymbolAddress((void**)&emb,   g_emb);
    cudaGetSymbolAddress((void**)&xw,    g_xw);
    cudaGetSymbolAddress((void**)&w1,    g_w1);
    cudaGetSymbolAddress((void**)&ip,    g_ip);
    cudaGetSymbolAddress((void**)&wt,    g_wt);
    cudaGetSymbolAddress((void**)&wf,    g_wf);

    // init
    cudaMemsetAsync(c_cur, 0, sizeof(float) * NL * CELLS * HD, 0);
    cudaMemsetAsync(h_cur, 0, sizeof(float) * NL * CELLS * HD, 0);
    cudaMemsetAsync(ip,    0, sizeof(float) * CELLS, 0);
    ipinit_kernel<<<1, 32>>>(ip);
    gather_kernel<<<(CELLS*NT*HD + 255) / 256, 256>>>(data, embed, emb);
    wcat1_kernel<<<(256*512 + 255) / 256, 256>>>(Wi, Wh, w1);

    // precompute xw[cell*4+t][512] = emb @ Wi(layer0); M = CELLS*NT rows
    fused_gemm_lstm<<<(CELLS*NT)/32, 256>>>(
        emb, HD, nullptr, Wi,
        nullptr, 0, nullptr, nullptr, nullptr, nullptr,
        xw, 8, 0);

    for (int s = 0; s < MAXST; ++s) {
        for (int t = 0; t < NT; ++t) {
            const float* cin0 = (t == 0) ? c_cur : c_wrk;
            const float* hin0 = (t == 0) ? h_cur : h_wrk;
            // layer 0: z = xw(t) + h @ Wh0 ; gate
            fused_gemm_lstm<<<CELLS/32, 256>>>(
                hin0, HD, nullptr, Wh,
                xw + t*512, NT*512, bl,
                cin0, c_wrk, h_wrk,
                nullptr, 8, 1);
            // layer 1: z = h0 @ Wi1 + h1 @ Wh1 + b ; gate
            const float* cin1 = (t == 0) ? c_cur + LOFF : c_wrk + LOFF;
            const float* hin1 = (t == 0) ? h_cur + LOFF : h_wrk + LOFF;
            fused_gemm_lstm<<<CELLS/32, 256>>>(
                h_wrk, HD, hin1, w1,
                nullptr, 0, bl + 512,
                cin1, c_wrk + LOFF, h_wrk + LOFF,
                nullptr, 16, 1);
        }
        restore_kernel<<<NB, 256>>>(exi, c_wrk, h_wrk, c_cur, h_cur);
        branch_kernel<<<(CELLS*32 + 255) / 256, 256>>>(
            c_wrk, h_wrk, c_wrk + LOFF, h_wrk + LOFF, Wb, bb, ip, wt, wf);
        agg_kernel<<<CELLS, 128>>>(s, steps, tb, fb, wt, wf,
                                   c_wrk, h_wrk, c_cur, h_cur, ip);
    }

    final_kernel<<<NB, 256>>>(exi, c_cur, h_cur, Wo, bo, out);
}